// round 16
// baseline (speedup 1.0000x reference)
#include <cuda_runtime.h>
#include <cuda_fp16.h>
#include <cstdint>

#define MTOT 16384
#define FEMB 3072
#define FVIS 6
#define FBB  4
#define FKP  51
#define FTOT 3133
#define TDIM 256
#define KPAD 3200          // 25 * 128
#define BM 64
#define BN 256
#define BK 128
#define NSTEP (KPAD / BK)  // 25
#define A_B (BM * BK * 2)  // 16384 B
#define W_B (BN * BK * 2)  // 65536 B
#define NWBUF 3
#define SMEM_TOTAL (2 * A_B + NWBUF * W_B)  // 224 KB -> 1 CTA/SM

__device__ int g_count;    // active rows (front of g_rows)
__device__ int g_icount;   // inactive rows (back of g_rows)
__device__ int g_rows[MTOT];
__device__ __align__(16) __half g_Wh[TDIM * KPAD];

// ---------------------------------------------------------------- helpers
__device__ __forceinline__ uint32_t smem_u32(const void* p) {
    uint32_t a;
    asm("{ .reg .u64 t; cvta.to.shared.u64 t, %1; cvt.u32.u64 %0, t; }"
        : "=r"(a) : "l"(p));
    return a;
}

#define LDSM4(r0, r1, r2, r3, addr)                                          \
    asm volatile("ldmatrix.sync.aligned.m8n8.x4.shared.b16 {%0,%1,%2,%3}, [%4];" \
        : "=r"(r0), "=r"(r1), "=r"(r2), "=r"(r3) : "r"(addr))

#define MMA(c, a0, a1, a2, a3, b0, b1)                                       \
    asm volatile("mma.sync.aligned.m16n8k16.row.col.f32.f16.f16.f32 "        \
        "{%0,%1,%2,%3},{%4,%5,%6,%7},{%8,%9},{%0,%1,%2,%3};"                 \
        : "+f"((c)[0]), "+f"((c)[1]), "+f"((c)[2]), "+f"((c)[3])             \
        : "r"(a0), "r"(a1), "r"(a2), "r"(a3), "r"(b0), "r"(b1))

#define CP_ASYNC16(dst, src)                                                 \
    asm volatile("cp.async.cg.shared.global [%0], [%1], 16;"                 \
        :: "r"(dst), "l"(src) : "memory")
#define CP_COMMIT() asm volatile("cp.async.commit_group;" ::: "memory")
#define CP_WAIT1()  asm volatile("cp.async.wait_group 1;" ::: "memory")

__device__ __forceinline__ uint32_t h2u(__half2 v) {
    return *reinterpret_cast<uint32_t*>(&v);
}

// pack 8 floats -> 8 fp16 (one uint4)
__device__ __forceinline__ void pack8(const float* v, uint4& H) {
    __half2 h0 = __float22half2_rn(make_float2(v[0], v[1]));
    __half2 h1 = __float22half2_rn(make_float2(v[2], v[3]));
    __half2 h2 = __float22half2_rn(make_float2(v[4], v[5]));
    __half2 h3 = __float22half2_rn(make_float2(v[6], v[7]));
    H = make_uint4(h2u(h0), h2u(h1), h2u(h2), h2u(h3));
}

// 16-chunk swizzle for 256B rows: keep chunk's 128B half, XOR low 3 bits
__device__ __forceinline__ uint32_t swz16(uint32_t c, uint32_t r7) {
    return (c & 8u) | ((c ^ r7) & 7u);
}

__device__ __forceinline__ float tail_feat(
    const float* __restrict__ vis, const float* __restrict__ bb,
    const float* __restrict__ kp, int g, int f)
{
    int d = f - FEMB;
    if (d < FVIS)              return vis[(size_t)g * FVIS + d];
    if (d < FVIS + FBB)        return bb[(size_t)g * FBB + d - FVIS];
    if (d < FVIS + FBB + FKP)  return kp[(size_t)g * FKP + d - FVIS - FBB];
    return 0.f;
}

// ---------------------------------------------------------------------------
// Kernel 1: reset counters + convert W to padded fp16 (2 half2 pairs/thread)
// ---------------------------------------------------------------------------
__global__ void wconv(const float* __restrict__ W) {
    if (blockIdx.x == 0 && threadIdx.x == 0) { g_count = 0; g_icount = 0; }
#pragma unroll
    for (int u = 0; u < 2; u++) {
        int i = blockIdx.x * 512 + u * 256 + threadIdx.x;   // pair index
        if (i < TDIM * KPAD / 2) {
            int n = (2 * i) / KPAD, f = 2 * i - n * KPAD;
            float v0 = (f < FTOT)     ? W[(size_t)n * FTOT + f]     : 0.f;
            float v1 = (f + 1 < FTOT) ? W[(size_t)n * FTOT + f + 1] : 0.f;
            reinterpret_cast<__half2*>(g_Wh)[i] = __floats2half2_rn(v0, v1);
        }
    }
}

// ---------------------------------------------------------------------------
// Kernel 2: bidirectional compaction (actives -> front, inactives -> back)
// ---------------------------------------------------------------------------
__global__ void compact(const int* __restrict__ mask) {
    int m = blockIdx.x * blockDim.x + threadIdx.x;
    bool act = (mask[m] != 0);
    unsigned bal = __ballot_sync(0xFFFFFFFFu, act);
    int lane = threadIdx.x & 31;
    int nact = __popc(bal);
    int baseA = 0, baseI = 0;
    if (lane == 0) {
        if (nact)      baseA = atomicAdd(&g_count, nact);
        if (nact < 32) baseI = atomicAdd(&g_icount, 32 - nact);
    }
    baseA = __shfl_sync(0xFFFFFFFFu, baseA, 0);
    baseI = __shfl_sync(0xFFFFFFFFu, baseI, 0);
    unsigned lt = (1u << lane) - 1u;
    if (act) g_rows[baseA + __popc(bal & lt)] = m;
    else     g_rows[MTOT - 1 - (baseI + __popc(~bal & lt))] = m;
}

// ---------------------------------------------------------------------------
// Kernel 3: fp16 GEMM via mma.sync, 64x256 CTA tile, BK=128, 512 thr, 1 CTA/SM.
// Warps 2m x 4n x 2k (warp tile 32x64 over half of BK); k-split reduced in
// smem. Idle/boundary CTAs zero inactive output rows in parallel.
// ---------------------------------------------------------------------------
__global__ __launch_bounds__(512, 1) void gemm_mma(
    const float* __restrict__ emb, const float* __restrict__ vis,
    const float* __restrict__ bb,  const float* __restrict__ kp,
    const float* __restrict__ bias, float* __restrict__ out)
{
    extern __shared__ char smem[];
    const int cnt = g_count;
    const int row0 = blockIdx.x * BM;
    const int tid = threadIdx.x;

    // ---- zero inactive rows in this CTA's position range ----
    {
        const int zs = max(row0, cnt);
        const int ze = row0 + BM;
        if (zs < ze) {
            const float4 z = make_float4(0.f, 0.f, 0.f, 0.f);
            const int nz = ze - zs;
            for (int t = tid; t < nz * 64; t += 512) {
                int g = g_rows[zs + t / 64];
                ((float4*)(out + (size_t)g * TDIM))[t & 63] = z;
            }
        }
    }
    if (row0 >= cnt) return;

    const int lane = tid & 31;
    const int wid = tid >> 5;         // 0..15
    const int wk = wid >> 3;          // 0..1  k-half
    const int wm = (wid >> 2) & 1;    // 0..1  32-row half
    const int wn = wid & 3;           // 0..3  64-col quarter

    const uint32_t sbase = smem_u32(smem);
    const uint32_t sW = sbase + 2 * A_B;      // 3 W tiles follow the A buffers

    // ---- A loader: 8 threads per row, 16 features each ----
    const int lrA = tid >> 3;                 // 0..63
    const int lhA = (tid & 7) * 16;
    const int ga = g_rows[min(row0 + lrA, cnt - 1)];
    const float* arow = emb + (size_t)ga * FEMB;
    uint32_t stsA[2];
#pragma unroll
    for (int q = 0; q < 2; q++)
        stsA[q] = (uint32_t)lrA * 256 +
                  (swz16((uint32_t)(lhA >> 3) + q, (uint32_t)(lrA & 7)) << 4);

    // ---- W loader: 2 threads per row (256 rows), 64 features each ----
    const int lrW = tid >> 1;                 // 0..255
    const int lhW = (tid & 1) * 64;
    const __half* wrow = g_Wh + (size_t)lrW * KPAD;
    uint32_t stsW[8];
#pragma unroll
    for (int q = 0; q < 8; q++)
        stsW[q] = (uint32_t)lrW * 256 +
                  (swz16((uint32_t)(lhW >> 3) + q, (uint32_t)(lrW & 7)) << 4);

    // ---- ldmatrix per-thread addressing ----
    const uint32_t lane7 = (uint32_t)(lane & 7);
    const uint32_t aRow  = (uint32_t)(wm * 32 + (lane & 15));
    const uint32_t aSel  = (uint32_t)(lane >> 4);
    const uint32_t bRow  = (uint32_t)(wn * 64 + (lane & 7) + ((lane >> 4) << 3));
    const uint32_t bSel  = (uint32_t)((lane >> 3) & 1);

    float acc[2][8][4];
#pragma unroll
    for (int i = 0; i < 2; i++)
#pragma unroll
        for (int j = 0; j < 8; j++)
#pragma unroll
            for (int q = 0; q < 4; q++) acc[i][j][q] = 0.f;

    float a[16];

    auto prefetchA = [&](int s) {
        const int f = s * BK + lhA;
        if (f + 16 <= FEMB) {
            const float4* p = (const float4*)(arow + f);
#pragma unroll
            for (int q = 0; q < 4; q++) *(float4*)(a + 4 * q) = p[q];
        } else {
#pragma unroll
            for (int e = 0; e < 16; e++) {
                int ff = f + e;
                a[e] = (ff < FEMB) ? arow[ff] : tail_feat(vis, bb, kp, ga, ff);
            }
        }
    };

    auto packA = [&](int s) {            // a[] -> A buffer (s & 1)
        char* abuf = smem + (uint32_t)(s & 1) * A_B;
        uint4 H[2];
        pack8(a,     H[0]);
        pack8(a + 8, H[1]);
#pragma unroll
        for (int q = 0; q < 2; q++) *(uint4*)(abuf + stsA[q]) = H[q];
    };

    auto issueW = [&](int s) {
        if (s < NSTEP) {
            uint32_t base = sW + (uint32_t)(s % NWBUF) * W_B;
            const __half* sh = wrow + s * BK + lhW;
#pragma unroll
            for (int q = 0; q < 8; q++)
                CP_ASYNC16(base + stsW[q], sh + 8 * q);
        }
        CP_COMMIT();
    };

    // prologue: W0, W1 in flight; A0 packed; A1 in registers
    issueW(0);
    issueW(1);
    prefetchA(0);
    packA(0);
    prefetchA(1);

    for (int s = 0; s < NSTEP; ++s) {
        CP_WAIT1();              // W(s) complete (W(s+1) may be pending)
        __syncthreads();         // publish A(s) stores + everyone's W(s)
        issueW(s + 2);           // slot (s+2)%3 held W(s-1): all reads pre-sync

        const uint32_t pA = sbase + (uint32_t)(s & 1) * A_B;
        const uint32_t pW = sW + (uint32_t)(s % NWBUF) * W_B;

#pragma unroll
        for (int kk = 0; kk < 4; kk++) {
            const uint32_t kidx = (uint32_t)(wk * 4 + kk);   // my k16 chunk 0..7
            const uint32_t cA = swz16(kidx * 2 + aSel, lane7);
            const uint32_t cB = swz16(kidx * 2 + bSel, lane7);

            uint32_t bh[16];
            const uint32_t b0 = bRow * 256 + (cB << 4);
            LDSM4(bh[0],  bh[1],  bh[2],  bh[3],  pW + b0);
            LDSM4(bh[4],  bh[5],  bh[6],  bh[7],  pW + b0 + 16 * 256);
            LDSM4(bh[8],  bh[9],  bh[10], bh[11], pW + b0 + 32 * 256);
            LDSM4(bh[12], bh[13], bh[14], bh[15], pW + b0 + 48 * 256);

#pragma unroll
            for (int mt = 0; mt < 2; mt++) {
                const uint32_t aA = (aRow + mt * 16) * 256 + (cA << 4);
                uint32_t a0, a1, a2, a3;
                LDSM4(a0, a1, a2, a3, pA + aA);
#pragma unroll
                for (int nt = 0; nt < 8; nt++) {
                    MMA(acc[mt][nt], a0, a1, a2, a3, bh[2 * nt], bh[2 * nt + 1]);
                }
            }
        }

        // off-critical-path: next A store + following A loads
        if (s + 1 < NSTEP) packA(s + 1);
        if (s + 2 < NSTEP) prefetchA(s + 2);
    }

    // ---------------- epilogue: k-split reduction + bias + scatter ----------
    float* red = (float*)(smem + 2 * A_B);    // 8 pairs x 8KB = 64KB (< W ring)
    const int pairIdx = (wm << 2) | wn;       // 0..7
    __syncthreads();                          // all MMAs done, W region free
    if (wk == 1) {
#pragma unroll
        for (int mt = 0; mt < 2; mt++)
#pragma unroll
            for (int nt = 0; nt < 8; nt++) {
                float* dst = red + pairIdx * 2048 + (mt * 8 + nt) * 128 + lane * 4;
                *(float4*)dst = *(float4*)acc[mt][nt];
            }
    }
    __syncthreads();
    if (wk == 0) {
#pragma unroll
        for (int mt = 0; mt < 2; mt++) {
            const int mlo = wm * 32 + mt * 16 + (lane >> 2);
            const int r1 = row0 + mlo;
            const int r2 = r1 + 8;
#pragma unroll
            for (int nt = 0; nt < 8; nt++) {
                const float* src = red + pairIdx * 2048 + (mt * 8 + nt) * 128 + lane * 4;
                float4 p = *(const float4*)src;
                const int c = wn * 64 + nt * 8 + (lane & 3) * 2;
                const float2 bv = *(const float2*)(bias + c);
                if (r1 < cnt) {
                    const int g = g_rows[r1];
                    float2 o = make_float2(acc[mt][nt][0] + p.x + bv.x,
                                           acc[mt][nt][1] + p.y + bv.y);
                    *(float2*)(out + (size_t)g * TDIM + c) = o;
                }
                if (r2 < cnt) {
                    const int g = g_rows[r2];
                    float2 o = make_float2(acc[mt][nt][2] + p.z + bv.x,
                                           acc[mt][nt][3] + p.w + bv.y);
                    *(float2*)(out + (size_t)g * TDIM + c) = o;
                }
            }
        }
    }
}

// ---------------------------------------------------------------------------
extern "C" void kernel_launch(void* const* d_in, const int* in_sizes, int n_in,
                              void* d_out, int out_size) {
    const float* emb  = (const float*)d_in[0];
    const float* vis  = (const float*)d_in[1];
    const float* bb   = (const float*)d_in[2];
    const float* kp   = (const float*)d_in[3];
    const int*   mask = (const int*)d_in[4];
    const float* W    = (const float*)d_in[5];
    const float* bias = (const float*)d_in[6];
    float*       out  = (float*)d_out;

    static bool configured = false;
    if (!configured) {
        cudaFuncSetAttribute(gemm_mma, cudaFuncAttributeMaxDynamicSharedMemorySize,
                             SMEM_TOTAL);
        configured = true;
    }

    wconv<<<(TDIM * KPAD / 2 + 511) / 512, 256>>>(W);
    compact<<<MTOT / 256, 256>>>(mask);
    gemm_mma<<<MTOT / BM, 512, SMEM_TOTAL>>>(emb, vis, bb, kp, bias, out);
}

// round 17
// speedup vs baseline: 1.6089x; 1.6089x over previous
#include <cuda_runtime.h>
#include <cuda_fp16.h>
#include <cstdint>

#define MTOT 16384
#define FEMB 3072
#define FVIS 6
#define FBB  4
#define FKP  51
#define FTOT 3133
#define TDIM 256
#define KPAD 3136          // 49 * 64
#define BM 64
#define BN 256
#define BK 64
#define NSTEP (KPAD / BK)  // 49
#define A_B (BM * BK * 2)  // 8192 B
#define W_B (BN * BK * 2)  // 32768 B
#define NWBUF 4
#define SMEM_TOTAL (2 * A_B + NWBUF * W_B)  // 144 KB -> 1 CTA/SM

#define NCBLK 64                        // compact blocks
#define NWBLK (TDIM * KPAD / 2 / 512)   // 784 wconv blocks (2 pairs/thread)

__device__ int g_cnt2[2];  // [0]=active count (front), [1]=inactive count (back)
__device__ int g_rows[MTOT];
__device__ __align__(16) __half g_Wh[TDIM * KPAD];

// ---------------------------------------------------------------- helpers
__device__ __forceinline__ uint32_t smem_u32(const void* p) {
    uint32_t a;
    asm("{ .reg .u64 t; cvta.to.shared.u64 t, %1; cvt.u32.u64 %0, t; }"
        : "=r"(a) : "l"(p));
    return a;
}

#define LDSM4(r0, r1, r2, r3, addr)                                          \
    asm volatile("ldmatrix.sync.aligned.m8n8.x4.shared.b16 {%0,%1,%2,%3}, [%4];" \
        : "=r"(r0), "=r"(r1), "=r"(r2), "=r"(r3) : "r"(addr))

#define MMA(c, a0, a1, a2, a3, b0, b1)                                       \
    asm volatile("mma.sync.aligned.m16n8k16.row.col.f32.f16.f16.f32 "        \
        "{%0,%1,%2,%3},{%4,%5,%6,%7},{%8,%9},{%0,%1,%2,%3};"                 \
        : "+f"((c)[0]), "+f"((c)[1]), "+f"((c)[2]), "+f"((c)[3])             \
        : "r"(a0), "r"(a1), "r"(a2), "r"(a3), "r"(b0), "r"(b1))

#define CP_ASYNC16(dst, src)                                                 \
    asm volatile("cp.async.cg.shared.global [%0], [%1], 16;"                 \
        :: "r"(dst), "l"(src) : "memory")
#define CP_COMMIT() asm volatile("cp.async.commit_group;" ::: "memory")
#define CP_WAIT2()  asm volatile("cp.async.wait_group 2;" ::: "memory")

__device__ __forceinline__ uint32_t h2u(__half2 v) {
    return *reinterpret_cast<uint32_t*>(&v);
}

// pack 8 floats -> 8 fp16 (one uint4)
__device__ __forceinline__ void pack8(const float* v, uint4& H) {
    __half2 h0 = __float22half2_rn(make_float2(v[0], v[1]));
    __half2 h1 = __float22half2_rn(make_float2(v[2], v[3]));
    __half2 h2 = __float22half2_rn(make_float2(v[4], v[5]));
    __half2 h3 = __float22half2_rn(make_float2(v[6], v[7]));
    H = make_uint4(h2u(h0), h2u(h1), h2u(h2), h2u(h3));
}

__device__ __forceinline__ float tail_feat(
    const float* __restrict__ vis, const float* __restrict__ bb,
    const float* __restrict__ kp, int g, int f)
{
    int d = f - FEMB;
    if (d < FVIS)              return vis[(size_t)g * FVIS + d];
    if (d < FVIS + FBB)        return bb[(size_t)g * FBB + d - FVIS];
    if (d < FVIS + FBB + FKP)  return kp[(size_t)g * FKP + d - FVIS - FBB];
    return 0.f;
}

// ---------------------------------------------------------------------------
// Kernel 1 (merged prep): blocks [0,NCBLK) compact rows bidirectionally;
// blocks [NCBLK, NCBLK+NWBLK) convert W to padded fp16. Counters are zeroed
// by a cudaMemsetAsync node before this kernel.
// ---------------------------------------------------------------------------
__global__ void prep(const int* __restrict__ mask, const float* __restrict__ W) {
    if (blockIdx.x < NCBLK) {
        int m = blockIdx.x * blockDim.x + threadIdx.x;
        bool act = (mask[m] != 0);
        unsigned bal = __ballot_sync(0xFFFFFFFFu, act);
        int lane = threadIdx.x & 31;
        int nact = __popc(bal);
        int baseA = 0, baseI = 0;
        if (lane == 0) {
            if (nact)      baseA = atomicAdd(&g_cnt2[0], nact);
            if (nact < 32) baseI = atomicAdd(&g_cnt2[1], 32 - nact);
        }
        baseA = __shfl_sync(0xFFFFFFFFu, baseA, 0);
        baseI = __shfl_sync(0xFFFFFFFFu, baseI, 0);
        unsigned lt = (1u << lane) - 1u;
        if (act) g_rows[baseA + __popc(bal & lt)] = m;
        else     g_rows[MTOT - 1 - (baseI + __popc(~bal & lt))] = m;
    } else {
        int b = blockIdx.x - NCBLK;
#pragma unroll
        for (int u = 0; u < 2; u++) {
            int i = b * 512 + u * 256 + threadIdx.x;   // half2-pair index
            int n = (2 * i) / KPAD, f = 2 * i - n * KPAD;
            float v0 = (f < FTOT)     ? W[(size_t)n * FTOT + f]     : 0.f;
            float v1 = (f + 1 < FTOT) ? W[(size_t)n * FTOT + f + 1] : 0.f;
            reinterpret_cast<__half2*>(g_Wh)[i] = __floats2half2_rn(v0, v1);
        }
    }
}

// ---------------------------------------------------------------------------
// Kernel 2: fp16 GEMM via mma.sync, 64x256 CTA tile, 512 thr, 1 CTA/SM.
// Warps 2m x 4n x 2k (warp tile 32x64, half of BK); k-split reduced in smem.
// Idle/boundary CTAs zero inactive output rows in parallel with compute.
// ---------------------------------------------------------------------------
__global__ __launch_bounds__(512, 1) void gemm_mma(
    const float* __restrict__ emb, const float* __restrict__ vis,
    const float* __restrict__ bb,  const float* __restrict__ kp,
    const float* __restrict__ bias, float* __restrict__ out)
{
    extern __shared__ char smem[];
    const int cnt = g_cnt2[0];
    const int row0 = blockIdx.x * BM;
    const int tid = threadIdx.x;

    // ---- zero inactive rows in this CTA's position range ----
    {
        const int zs = max(row0, cnt);
        const int ze = row0 + BM;
        if (zs < ze) {
            const float4 z = make_float4(0.f, 0.f, 0.f, 0.f);
            const int nz = ze - zs;
            for (int t = tid; t < nz * 64; t += 512) {
                int g = g_rows[zs + t / 64];
                ((float4*)(out + (size_t)g * TDIM))[t & 63] = z;
            }
        }
    }
    if (row0 >= cnt) return;

    const int lane = tid & 31;
    const int wid = tid >> 5;         // 0..15
    const int wk = wid >> 3;          // 0..1  k-half
    const int wm = (wid >> 2) & 1;    // 0..1  32-row half
    const int wn = wid & 3;           // 0..3  64-col quarter

    const uint32_t sbase = smem_u32(smem);
    const uint32_t sW = sbase + 2 * A_B;      // 4 W tiles follow the A buffers

    // ---- A loader: 8 threads per row, 8 features each ----
    const int lrA = tid >> 3;                 // 0..63
    const int lhA = (tid & 7) * 8;
    const int ga = g_rows[min(row0 + lrA, cnt - 1)];
    const float* arow = emb + (size_t)ga * FEMB;
    const uint32_t stsA = (uint32_t)lrA * 128 +
        ((((uint32_t)(lhA >> 3)) ^ (uint32_t)(lrA & 7)) << 4);

    // ---- W loader: 2 threads per row (256 rows), 32 features each ----
    const int lrW = tid >> 1;                 // 0..255
    const int lhW = (tid & 1) * 32;
    const __half* wrow = g_Wh + (size_t)lrW * KPAD;
    uint32_t stsW[4];
#pragma unroll
    for (int q = 0; q < 4; q++)
        stsW[q] = (uint32_t)lrW * 128 +
                  ((((uint32_t)(lhW >> 3) + q) ^ (uint32_t)(lrW & 7)) << 4);

    // ---- ldmatrix per-thread addressing ----
    const uint32_t lane7 = (uint32_t)(lane & 7);
    const uint32_t aRow  = (uint32_t)(wm * 32 + (lane & 15));
    const uint32_t aSel  = (uint32_t)(lane >> 4);
    const uint32_t bRow  = (uint32_t)(wn * 64 + (lane & 7) + ((lane >> 4) << 3));
    const uint32_t bSel  = (uint32_t)((lane >> 3) & 1);

    float acc[2][8][4];
#pragma unroll
    for (int i = 0; i < 2; i++)
#pragma unroll
        for (int j = 0; j < 8; j++)
#pragma unroll
            for (int q = 0; q < 4; q++) acc[i][j][q] = 0.f;

    float a[8];

    auto prefetchA = [&](int s) {
        const int f = s * BK + lhA;
        if (f + 8 <= FEMB) {
            const float4* p = (const float4*)(arow + f);
            *(float4*)(a + 0) = p[0];
            *(float4*)(a + 4) = p[1];
        } else {
#pragma unroll
            for (int e = 0; e < 8; e++) {
                int ff = f + e;
                a[e] = (ff < FEMB) ? arow[ff] : tail_feat(vis, bb, kp, ga, ff);
            }
        }
    };

    auto packA = [&](int s) {            // a[] -> A buffer (s & 1)
        char* abuf = smem + (uint32_t)(s & 1) * A_B;
        uint4 H;
        pack8(a, H);
        *(uint4*)(abuf + stsA) = H;
    };

    auto issueW = [&](int s) {
        if (s < NSTEP) {
            uint32_t base = sW + (uint32_t)(s & 3) * W_B;
            const __half* sh = wrow + s * BK + lhW;
#pragma unroll
            for (int q = 0; q < 4; q++)
                CP_ASYNC16(base + stsW[q], sh + 8 * q);
        }
        CP_COMMIT();
    };

    // prologue: W0, W1 in flight; A0 packed; A1 in registers
    issueW(0);
    issueW(1);
    prefetchA(0);
    packA(0);
    prefetchA(1);

    for (int s = 0; s < NSTEP; ++s) {
        // slot (s+2)&3 held W(s-2); all its readers passed barrier(s-1) -> safe
        issueW(s + 2);
        CP_WAIT2();              // groups W0..W(s+2); <=2 pending => W(s) done
        __syncthreads();         // publish A(s) stores + everyone's W(s)

        const uint32_t pA = sbase + (uint32_t)(s & 1) * A_B;
        const uint32_t pW = sW + (uint32_t)(s & 3) * W_B;

#pragma unroll
        for (int kk = 0; kk < 2; kk++) {
            const uint32_t kidx = (uint32_t)(wk * 2 + kk);   // my k16 chunk
            const uint32_t cA = (kidx * 2 + aSel) ^ lane7;
            const uint32_t cB = (kidx * 2 + bSel) ^ lane7;

            uint32_t bh[16];
            const uint32_t b0 = bRow * 128 + (cB << 4);
            LDSM4(bh[0],  bh[1],  bh[2],  bh[3],  pW + b0);
            LDSM4(bh[4],  bh[5],  bh[6],  bh[7],  pW + b0 + 16 * 128);
            LDSM4(bh[8],  bh[9],  bh[10], bh[11], pW + b0 + 32 * 128);
            LDSM4(bh[12], bh[13], bh[14], bh[15], pW + b0 + 48 * 128);

#pragma unroll
            for (int mt = 0; mt < 2; mt++) {
                const uint32_t aA = (aRow + mt * 16) * 128 + (cA << 4);
                uint32_t a0, a1, a2, a3;
                LDSM4(a0, a1, a2, a3, pA + aA);
#pragma unroll
                for (int nt = 0; nt < 8; nt++) {
                    MMA(acc[mt][nt], a0, a1, a2, a3, bh[2 * nt], bh[2 * nt + 1]);
                }
            }
        }

        // off-critical-path: next A store + following A loads
        if (s + 1 < NSTEP) packA(s + 1);
        if (s + 2 < NSTEP) prefetchA(s + 2);
    }

    // ---------------- epilogue: k-split reduction + bias + scatter ----------
    float* red = (float*)(smem + 2 * A_B);    // 8 pairs x 8KB = 64KB (< W ring)
    const int pairIdx = (wm << 2) | wn;       // 0..7
    __syncthreads();                          // all MMAs done, W region free
    if (wk == 1) {
#pragma unroll
        for (int mt = 0; mt < 2; mt++)
#pragma unroll
            for (int nt = 0; nt < 8; nt++) {
                float* dst = red + pairIdx * 2048 + (mt * 8 + nt) * 128 + lane * 4;
                *(float4*)dst = *(float4*)acc[mt][nt];
            }
    }
    __syncthreads();
    if (wk == 0) {
#pragma unroll
        for (int mt = 0; mt < 2; mt++) {
            const int mlo = wm * 32 + mt * 16 + (lane >> 2);
            const int r1 = row0 + mlo;
            const int r2 = r1 + 8;
#pragma unroll
            for (int nt = 0; nt < 8; nt++) {
                const float* src = red + pairIdx * 2048 + (mt * 8 + nt) * 128 + lane * 4;
                float4 p = *(const float4*)src;
                const int c = wn * 64 + nt * 8 + (lane & 3) * 2;
                const float2 bv = *(const float2*)(bias + c);
                if (r1 < cnt) {
                    const int g = g_rows[r1];
                    float2 o = make_float2(acc[mt][nt][0] + p.x + bv.x,
                                           acc[mt][nt][1] + p.y + bv.y);
                    *(float2*)(out + (size_t)g * TDIM + c) = o;
                }
                if (r2 < cnt) {
                    const int g = g_rows[r2];
                    float2 o = make_float2(acc[mt][nt][2] + p.z + bv.x,
                                           acc[mt][nt][3] + p.w + bv.y);
                    *(float2*)(out + (size_t)g * TDIM + c) = o;
                }
            }
        }
    }
}

// ---------------------------------------------------------------------------
extern "C" void kernel_launch(void* const* d_in, const int* in_sizes, int n_in,
                              void* d_out, int out_size) {
    const float* emb  = (const float*)d_in[0];
    const float* vis  = (const float*)d_in[1];
    const float* bb   = (const float*)d_in[2];
    const float* kp   = (const float*)d_in[3];
    const int*   mask = (const int*)d_in[4];
    const float* W    = (const float*)d_in[5];
    const float* bias = (const float*)d_in[6];
    float*       out  = (float*)d_out;

    static void* cnt_addr = nullptr;
    if (!cnt_addr) {
        cudaGetSymbolAddress(&cnt_addr, g_cnt2);
        cudaFuncSetAttribute(gemm_mma, cudaFuncAttributeMaxDynamicSharedMemorySize,
                             SMEM_TOTAL);
    }

    cudaMemsetAsync(cnt_addr, 0, 2 * sizeof(int));
    prep<<<NCBLK + NWBLK, 256>>>(mask, W);
    gemm_mma<<<MTOT / BM, 512, SMEM_TOTAL>>>(emb, vis, bb, kp, bias, out);
}